// round 9
// baseline (speedup 1.0000x reference)
#include <cuda_runtime.h>
#include <cuda_bf16.h>
#include <cstdint>

// Problem constants
#define Bq   64
#define Kk   4096
#define Dd   512
#define Hh   512

// Scratch (no cudaMalloc allowed)
__device__ float g_qh[Bq * Hh];
__device__ float g_kh[Kk * Hh];
__device__ float g_part[4 * Bq * Kk];                    // 4 h-quarter partials
__device__ __align__(16) __nv_bfloat16 g_Ah[Kk * Dd];    // key hi
__device__ __align__(16) __nv_bfloat16 g_Al[Kk * Dd];    // key lo
__device__ __align__(16) __nv_bfloat16 g_Bth[Hh * Dd];   // W1b^T hi  [n][k]
__device__ __align__(16) __nv_bfloat16 g_Btl[Hh * Dd];   // W1b^T lo  [n][k]

// ---------------------------------------------------------------------------
// f32x2 packed helpers
// ---------------------------------------------------------------------------
__device__ __forceinline__ unsigned long long pack2(float x, float y) {
    unsigned long long r;
    asm("mov.b64 %0, {%1, %2};" : "=l"(r) : "r"(__float_as_uint(x)), "r"(__float_as_uint(y)));
    return r;
}
__device__ __forceinline__ void fma2(unsigned long long& d,
                                     unsigned long long a, unsigned long long b) {
    asm("fma.rn.f32x2 %0, %1, %2, %0;" : "+l"(d) : "l"(a), "l"(b));
}
__device__ __forceinline__ unsigned long long add2(unsigned long long a,
                                                   unsigned long long b) {
    unsigned long long r;
    asm("add.rn.f32x2 %0, %1, %2;" : "=l"(r) : "l"(a), "l"(b));
    return r;
}
__device__ __forceinline__ float2 unpack2(unsigned long long v) {
    unsigned int lo, hi;
    asm("mov.b64 {%0, %1}, %2;" : "=r"(lo), "=r"(hi) : "l"(v));
    return make_float2(__uint_as_float(lo), __uint_as_float(hi));
}

// fp32 -> (hi, lo) bf16 split
__device__ __forceinline__ void split_bf16(float x, unsigned short& hi, unsigned short& lo) {
    __nv_bfloat16 h = __float2bfloat16_rn(x);
    float r = x - __bfloat162float(h);
    __nv_bfloat16 l = __float2bfloat16_rn(r);
    hi = __bfloat16_as_ushort(h);
    lo = __bfloat16_as_ushort(l);
}

__device__ __forceinline__ uint32_t smem_u32(const void* p) {
    uint32_t a;
    asm("{ .reg .u64 t; cvta.to.shared.u64 t, %1; cvt.u32.u64 %0, t; }" : "=r"(a) : "l"(p));
    return a;
}

// ---------------------------------------------------------------------------
// mma.sync helpers (sm_80 PTX — safe on the sm_100 ptxas target)
// ---------------------------------------------------------------------------
__device__ __forceinline__ void ldmx4(uint32_t* r, uint32_t addr) {
    asm volatile("ldmatrix.sync.aligned.m8n8.x4.shared.b16 {%0,%1,%2,%3}, [%4];"
        : "=r"(r[0]), "=r"(r[1]), "=r"(r[2]), "=r"(r[3]) : "r"(addr));
}
__device__ __forceinline__ void mma_bf16(float* c, const uint32_t* a, const uint32_t* b) {
    asm volatile("mma.sync.aligned.m16n8k16.row.col.f32.bf16.bf16.f32 "
        "{%0,%1,%2,%3}, {%4,%5,%6,%7}, {%8,%9}, {%0,%1,%2,%3};"
        : "+f"(c[0]), "+f"(c[1]), "+f"(c[2]), "+f"(c[3])
        : "r"(a[0]), "r"(a[1]), "r"(a[2]), "r"(a[3]), "r"(b[0]), "r"(b[1]));
}

// ---------------------------------------------------------------------------
// Kernel 1 (convert + qh), 3 roles by blockIdx:
//   [0,256)   : split key_embed -> g_Ah/g_Al (coalesced)
//   [256,512) : transpose+split W1[D:] -> g_Bth/g_Btl
//   [512,544) : qh = gather(query_embed) @ W1[:D]  (SIMT f32x2)
// ---------------------------------------------------------------------------
__global__ __launch_bounds__(256) void convert_kernel(const int* __restrict__ Xq,
                                                      const float* __restrict__ qemb,
                                                      const float* __restrict__ kemb,
                                                      const float* __restrict__ W1) {
    __shared__ union {
        float tr[32][33];
        float qs[Dd][4];
    } sm;
    int t = threadIdx.x;
    int bid = blockIdx.x;

    if (bid < 256) {
        // ---- role A: split key_embed (2M floats, 8192 per block) ----
#pragma unroll
        for (int j = 0; j < 8; ++j) {
            size_t i = (size_t)bid * 8192 + j * 1024 + t * 4;
            float4 v = *(const float4*)&kemb[i];
            unsigned short h0, l0, h1, l1, h2, l2, h3, l3;
            split_bf16(v.x, h0, l0); split_bf16(v.y, h1, l1);
            split_bf16(v.z, h2, l2); split_bf16(v.w, h3, l3);
            *(unsigned long long*)&g_Ah[i] =
                (unsigned long long)h0 | ((unsigned long long)h1 << 16) |
                ((unsigned long long)h2 << 32) | ((unsigned long long)h3 << 48);
            *(unsigned long long*)&g_Al[i] =
                (unsigned long long)l0 | ((unsigned long long)l1 << 16) |
                ((unsigned long long)l2 << 32) | ((unsigned long long)l3 << 48);
        }
    } else if (bid < 512) {
        // ---- role B: transpose+split W1b 32x32 tiles ----
        const float* W1b = W1 + (size_t)Dd * Hh;
        int tt = bid - 256;
        int kb = (tt >> 4) * 32;
        int nb = (tt & 15) * 32;
        int r  = t >> 3;
        int c4 = (t & 7) * 4;
        float4 v = *(const float4*)&W1b[(size_t)(kb + r) * Hh + nb + c4];
        sm.tr[r][c4 + 0] = v.x; sm.tr[r][c4 + 1] = v.y;
        sm.tr[r][c4 + 2] = v.z; sm.tr[r][c4 + 3] = v.w;
        __syncthreads();
        unsigned long long hv = 0, lv = 0;
#pragma unroll
        for (int j = 0; j < 4; ++j) {
            unsigned short h, l;
            split_bf16(sm.tr[c4 + j][r], h, l);
            hv |= (unsigned long long)h << (16 * j);
            lv |= (unsigned long long)l << (16 * j);
        }
        size_t o = (size_t)(nb + r) * Dd + kb + c4;
        *(unsigned long long*)&g_Bth[o] = hv;
        *(unsigned long long*)&g_Btl[o] = lv;
    } else {
        // ---- role qh: 4 b x 256 h per block (exact fp32) ----
        int r  = bid - 512;
        int hc = r & 1;
        int bg = r >> 1;
        int h  = hc * 256 + t;
        int b0 = bg * 4;

        int bi   = t >> 6;
        int lane64 = t & 63;
        const float* qrow = qemb + (size_t)Xq[b0 + bi] * Dd;
#pragma unroll
        for (int j = 0; j < 8; ++j) {
            int d = lane64 + 64 * j;
            sm.qs[d][bi] = qrow[d];
        }
        __syncthreads();

        const float* w = W1 + h;
        unsigned long long acc01 = 0ULL, acc23 = 0ULL;
#pragma unroll 8
        for (int d = 0; d < Dd; ++d) {
            float wv = w[(size_t)d * Hh];
            float4 q4 = *(const float4*)&sm.qs[d][0];
            unsigned long long ws = pack2(wv, wv);
            fma2(acc01, pack2(q4.x, q4.y), ws);
            fma2(acc23, pack2(q4.z, q4.w), ws);
        }
        float2 p01 = unpack2(acc01);
        float2 p23 = unpack2(acc23);
        g_qh[(b0 + 0) * Hh + h] = p01.x;
        g_qh[(b0 + 1) * Hh + h] = p01.y;
        g_qh[(b0 + 2) * Hh + h] = p23.x;
        g_qh[(b0 + 3) * Hh + h] = p23.y;
    }
}

// ---------------------------------------------------------------------------
// Kernel 2: kh' = key @ W1b + b1 via bf16 mma.sync, 3-term split:
//   seg0: Ah*Bh   seg1: Al*Bh   seg2: Ah*Bl    (residual Al*Bl ~ 2^-18)
// CTA tile 128x128, 8 warps (2m x 4n), warp tile 64x32 (4 m16 x 4 n8).
// Double-buffered smem, register-prefetched global loads.
// ---------------------------------------------------------------------------
#define APITCH 24                    // bf16 pitch: 48B rows, conflict-free ldmatrix
#define BUFE   (128 * APITCH)        // elements per buffer (3072)
#define BUFB   (BUFE * 2)            // bytes per buffer (6144)

__global__ __launch_bounds__(256, 1) void kh_gemm(const float* __restrict__ b1) {
    __shared__ __nv_bfloat16 smbuf[4 * BUFE];   // A0 A1 B0 B1 = 24 KB

    int t    = threadIdx.x;
    int wid  = t >> 5;
    int lane = t & 31;
    int m0 = (blockIdx.x >> 2) * 128;
    int n0 = (blockIdx.x & 3) * 128;
    int wm0 = (wid & 1) * 64;
    int wn0 = (wid >> 1) * 32;

    uint32_t sbase = smem_u32(smbuf);
    uint32_t sA = sbase;                 // A buffers (ldmatrix operand space)
    uint32_t sB = sbase + 2 * BUFB;      // B buffers

    // ldmatrix per-lane byte offsets (within one buffer)
    uint32_t aoff[4], boff[2];
#pragma unroll
    for (int mt = 0; mt < 4; ++mt)
        aoff[mt] = ((wm0 + mt * 16 + (lane & 15)) * APITCH + (lane >> 4) * 8) * 2;
    {
        int quad = lane >> 3, l8 = lane & 7;
#pragma unroll
        for (int p = 0; p < 2; ++p)
            boff[p] = ((wn0 + 16 * p + (quad >> 1) * 8 + l8) * APITCH + (quad & 1) * 8) * 2;
    }

    // staging mapping: row = t>>1, half = (t&1)*8  (16B-aligned: 48*row + 16*half8)
    int srow = t >> 1;
    int shalf = (t & 1) * 8;
    __nv_bfloat16* stA = &smbuf[srow * APITCH + shalf];            // A0
    __nv_bfloat16* stB = &smbuf[2 * BUFE + srow * APITCH + shalf]; // B0

    float acc[4][4][4];
#pragma unroll
    for (int i = 0; i < 4; ++i)
#pragma unroll
        for (int j = 0; j < 4; ++j)
#pragma unroll
            for (int p = 0; p < 4; ++p) acc[i][j][p] = 0.f;

    const __nv_bfloat16* Aplane[3] = {g_Ah, g_Al, g_Ah};
    const __nv_bfloat16* Bplane[3] = {g_Bth, g_Bth, g_Btl};

    // preload step 0 into buffer 0
    uint4 aR = *(const uint4*)&g_Ah[(size_t)(m0 + srow) * Dd + shalf];
    uint4 bR = *(const uint4*)&g_Bth[(size_t)(n0 + srow) * Dd + shalf];
    *(uint4*)stA = aR;
    *(uint4*)stB = bR;
    __syncthreads();

    const int NSTEP = 96;            // 3 segments x 32 k16-steps
    for (int s = 0; s < NSTEP; ++s) {
        int cur = s & 1;

        // prefetch next step's tiles into registers
        if (s + 1 < NSTEP) {
            int seg = (s + 1) >> 5;
            int kk  = ((s + 1) & 31) << 4;
            aR = *(const uint4*)&Aplane[seg][(size_t)(m0 + srow) * Dd + kk + shalf];
            bR = *(const uint4*)&Bplane[seg][(size_t)(n0 + srow) * Dd + kk + shalf];
        }

        // compute from buffer cur (ldmatrix uses shared-space u32 addresses)
        uint32_t a[4][4], bfr[4][2];
        uint32_t cA = sA + cur * BUFB;
        uint32_t cB = sB + cur * BUFB;
#pragma unroll
        for (int mt = 0; mt < 4; ++mt) ldmx4(a[mt], cA + aoff[mt]);
#pragma unroll
        for (int p = 0; p < 2; ++p) {
            uint32_t r[4];
            ldmx4(r, cB + boff[p]);
            bfr[2 * p][0] = r[0]; bfr[2 * p][1] = r[1];
            bfr[2 * p + 1][0] = r[2]; bfr[2 * p + 1][1] = r[3];
        }
#pragma unroll
        for (int mt = 0; mt < 4; ++mt)
#pragma unroll
            for (int nt = 0; nt < 4; ++nt)
                mma_bf16(acc[mt][nt], a[mt], bfr[nt]);

        // stage next step into the other buffer (generic pointers)
        if (s + 1 < NSTEP) {
            int nxt = cur ^ 1;
            *(uint4*)(stA + nxt * BUFE) = aR;
            *(uint4*)(stB + nxt * BUFE) = bR;
        }
        __syncthreads();
    }

    // epilogue: + b1 -> g_kh
#pragma unroll
    for (int mt = 0; mt < 4; ++mt) {
        int rg = m0 + wm0 + mt * 16 + (lane >> 2);
#pragma unroll
        for (int nt = 0; nt < 4; ++nt) {
            int ng = n0 + wn0 + nt * 8 + (lane & 3) * 2;
            float2 bv = *(const float2*)&b1[ng];
            *(float2*)&g_kh[(size_t)rg * Hh + ng] =
                make_float2(acc[mt][nt][0] + bv.x, acc[mt][nt][1] + bv.y);
            *(float2*)&g_kh[(size_t)(rg + 8) * Hh + ng] =
                make_float2(acc[mt][nt][2] + bv.x, acc[mt][nt][3] + bv.y);
        }
    }
}

// ---------------------------------------------------------------------------
// Kernel 3 (v3): logits partials over h-quarters (128 h each).
// Tile 64k x 32b, 256 threads (16 tk x 16 tb), thread = 4 contiguous k x 2 b.
// Double-buffered smem + register prefetch -> ONE barrier per 32-h chunk;
// w2 packed once; kk/qq each a single LDS.128. Exact packed relu
// (s + |s| = 2*relu(s)) with w/2 pre-folded. Grid 512 = 64kt x 2bt x 4hq.
// ---------------------------------------------------------------------------
#define CH 32

__global__ __launch_bounds__(256, 4) void logits_partial(const float* __restrict__ W2) {
    __shared__ float ks[2][CH][68];                  // [buf][h][k] 17.4 KB
    __shared__ unsigned long long qsp[2][CH][34];    // [buf][h][b] packed, 17.4 KB
    __shared__ unsigned long long w2p[128];          // packed (w/2, w/2), 1 KB

    const unsigned long long ABSM = 0x7FFFFFFF7FFFFFFFULL;

    int t  = threadIdx.x;
    int tk = t & 15;                 // k: 4 contiguous at k0 + 4*tk
    int tb = t >> 4;                 // b: 2 at b0 + 2*tb
    int bx = blockIdx.x;
    int kt = bx & 63;
    int bt = (bx >> 6) & 1;
    int hq = bx >> 7;
    int k0 = kt * 64;
    int b0 = bt * 32;
    int hbase = hq * 128;

    // w2 for this block's 128 h, packed with the 1/2 folded in
    if (t < 128) {
        float wv = W2[hbase + t] * 0.5f;
        w2p[t] = pack2(wv, wv);
    }

    // stage chunk 0 into buffer 0
#pragma unroll
    for (int i = 0; i < 8; ++i) {
        int lin = t + i * 256;                       // 0..2047
        int k = lin >> 5, hh = lin & 31;
        ks[0][hh][k] = g_kh[(size_t)(k0 + k) * Hh + hbase + hh];
    }
#pragma unroll
    for (int i = 0; i < 4; ++i) {
        int lin = t + i * 256;                       // 0..1023
        int b = lin >> 5, hh = lin & 31;
        float qv = g_qh[(b0 + b) * Hh + hbase + hh];
        qsp[0][hh][b] = pack2(qv, qv);
    }
    __syncthreads();

    unsigned long long acc[4] = {0ULL, 0ULL, 0ULL, 0ULL};

    for (int cc = 0; cc < 4; ++cc) {
        int cur = cc & 1;
        int nxt = cur ^ 1;

        // prefetch chunk cc+1 into registers (hidden under compute below)
        float pk[8], pq[4];
        if (cc < 3) {
            int h0n = hbase + (cc + 1) * CH;
#pragma unroll
            for (int i = 0; i < 8; ++i) {
                int lin = t + i * 256;
                int k = lin >> 5, hh = lin & 31;
                pk[i] = g_kh[(size_t)(k0 + k) * Hh + h0n + hh];
            }
#pragma unroll
            for (int i = 0; i < 4; ++i) {
                int lin = t + i * 256;
                int b = lin >> 5, hh = lin & 31;
                pq[i] = g_qh[(b0 + b) * Hh + h0n + hh];
            }
        }

        // compute chunk cc from buffer cur
#pragma unroll 8
        for (int hh = 0; hh < CH; ++hh) {
            uint4 kk = *(const uint4*)&ks[cur][hh][4 * tk];       // LDS.128
            uint4 qq = *(const uint4*)&qsp[cur][hh][2 * tb];      // LDS.128
            unsigned long long w2 = w2p[cc * CH + hh];            // LDS.64 bcast
            unsigned long long kk0 = ((unsigned long long)kk.y << 32) | kk.x;
            unsigned long long kk1 = ((unsigned long long)kk.w << 32) | kk.z;
            unsigned long long qq0 = ((unsigned long long)qq.y << 32) | qq.x;
            unsigned long long qq1 = ((unsigned long long)qq.w << 32) | qq.z;

            unsigned long long s;
            s = add2(qq0, kk0); s = add2(s, s & ABSM); fma2(acc[0], s, w2);
            s = add2(qq0, kk1); s = add2(s, s & ABSM); fma2(acc[1], s, w2);
            s = add2(qq1, kk0); s = add2(s, s & ABSM); fma2(acc[2], s, w2);
            s = add2(qq1, kk1); s = add2(s, s & ABSM); fma2(acc[3], s, w2);
        }

        // commit prefetched chunk into the other buffer
        if (cc < 3) {
#pragma unroll
            for (int i = 0; i < 8; ++i) {
                int lin = t + i * 256;
                int k = lin >> 5, hh = lin & 31;
                ks[nxt][hh][k] = pk[i];
            }
#pragma unroll
            for (int i = 0; i < 4; ++i) {
                int lin = t + i * 256;
                int b = lin >> 5, hh = lin & 31;
                qsp[nxt][hh][b] = pack2(pq[i], pq[i]);
            }
        }
        __syncthreads();
    }

    // partial write: 4 contiguous k per b
    float* base = &g_part[(size_t)hq * Bq * Kk];
    {
        int b = b0 + 2 * tb;
        float2 r0 = unpack2(acc[0]);
        float2 r1 = unpack2(acc[1]);
        *(float4*)&base[(size_t)b * Kk + k0 + 4 * tk] = make_float4(r0.x, r0.y, r1.x, r1.y);
        float2 r2 = unpack2(acc[2]);
        float2 r3 = unpack2(acc[3]);
        *(float4*)&base[(size_t)(b + 1) * Kk + k0 + 4 * tk] = make_float4(r2.x, r2.y, r3.x, r3.y);
    }
}

// ---------------------------------------------------------------------------
// Kernel 4 (v2): out = sum of 4 partials + b2.  float2 grain, 131k threads.
// ---------------------------------------------------------------------------
__global__ __launch_bounds__(256) void logits_reduce(const float* __restrict__ b2,
                                                     float* __restrict__ out) {
    int i = blockIdx.x * 256 + threadIdx.x;          // 131072 float2 slots
    const float2* p0 = (const float2*)&g_part[0 * Bq * Kk];
    const float2* p1 = (const float2*)&g_part[1 * Bq * Kk];
    const float2* p2 = (const float2*)&g_part[2 * Bq * Kk];
    const float2* p3 = (const float2*)&g_part[3 * Bq * Kk];
    float bias = b2[0];
    float2 a = p0[i], b = p1[i], c = p2[i], d = p3[i];
    ((float2*)out)[i] = make_float2(a.x + b.x + c.x + d.x + bias,
                                    a.y + b.y + c.y + d.y + bias);
}

// ---------------------------------------------------------------------------
// Inputs (metadata order): X_query(int32, 64), query_embed(f32, 8192x512),
// key_embed(f32, 4096x512), W1(f32, 1024x512), b1(f32, 512),
// W2(f32, 512x1), b2(f32, 1). Output: f32, 64x4096.
// ---------------------------------------------------------------------------
extern "C" void kernel_launch(void* const* d_in, const int* in_sizes, int n_in,
                              void* d_out, int out_size) {
    const int*   Xq   = (const int*)d_in[0];
    const float* qemb = (const float*)d_in[1];
    const float* kemb = (const float*)d_in[2];
    const float* W1   = (const float*)d_in[3];
    const float* b1   = (const float*)d_in[4];
    const float* W2   = (const float*)d_in[5];
    const float* b2   = (const float*)d_in[6];
    float* out = (float*)d_out;

    convert_kernel<<<544, 256>>>(Xq, qemb, kemb, W1);   // split A/B + qh
    kh_gemm<<<128, 256>>>(b1);                          // tensor-core kh
    logits_partial<<<512, 256>>>(W2);                   // h-split relu-reduce
    logits_reduce<<<512, 256>>>(b2, out);               // combine + b2
}

// round 10
// speedup vs baseline: 1.0405x; 1.0405x over previous
#include <cuda_runtime.h>
#include <cuda_bf16.h>
#include <cstdint>

// Problem constants
#define Bq   64
#define Kk   4096
#define Dd   512
#define Hh   512

// Scratch (no cudaMalloc allowed)
__device__ float g_qh[Bq * Hh];
__device__ float g_kh[Kk * Hh];
__device__ float g_part[4 * Bq * Kk];                    // 4 h-quarter partials
__device__ __align__(16) __nv_bfloat16 g_Ah[Kk * Dd];    // key hi
__device__ __align__(16) __nv_bfloat16 g_Al[Kk * Dd];    // key lo
__device__ __align__(16) __nv_bfloat16 g_Bth[Hh * Dd];   // W1b^T hi  [n][k]
__device__ __align__(16) __nv_bfloat16 g_Btl[Hh * Dd];   // W1b^T lo  [n][k]

// ---------------------------------------------------------------------------
// f32x2 packed helpers
// ---------------------------------------------------------------------------
__device__ __forceinline__ unsigned long long pack2(float x, float y) {
    unsigned long long r;
    asm("mov.b64 %0, {%1, %2};" : "=l"(r) : "r"(__float_as_uint(x)), "r"(__float_as_uint(y)));
    return r;
}
__device__ __forceinline__ void fma2(unsigned long long& d,
                                     unsigned long long a, unsigned long long b) {
    asm("fma.rn.f32x2 %0, %1, %2, %0;" : "+l"(d) : "l"(a), "l"(b));
}
__device__ __forceinline__ unsigned long long add2(unsigned long long a,
                                                   unsigned long long b) {
    unsigned long long r;
    asm("add.rn.f32x2 %0, %1, %2;" : "=l"(r) : "l"(a), "l"(b));
    return r;
}
__device__ __forceinline__ float2 unpack2(unsigned long long v) {
    unsigned int lo, hi;
    asm("mov.b64 {%0, %1}, %2;" : "=r"(lo), "=r"(hi) : "l"(v));
    return make_float2(__uint_as_float(lo), __uint_as_float(hi));
}

// fp32 -> (hi, lo) bf16 split
__device__ __forceinline__ void split_bf16(float x, unsigned short& hi, unsigned short& lo) {
    __nv_bfloat16 h = __float2bfloat16_rn(x);
    float r = x - __bfloat162float(h);
    __nv_bfloat16 l = __float2bfloat16_rn(r);
    hi = __bfloat16_as_ushort(h);
    lo = __bfloat16_as_ushort(l);
}

__device__ __forceinline__ uint32_t smem_u32(const void* p) {
    uint32_t a;
    asm("{ .reg .u64 t; cvta.to.shared.u64 t, %1; cvt.u32.u64 %0, t; }" : "=r"(a) : "l"(p));
    return a;
}

// ---------------------------------------------------------------------------
// mma.sync helpers (sm_80 PTX — safe on the sm_100 ptxas target)
// ---------------------------------------------------------------------------
__device__ __forceinline__ void ldmx4(uint32_t* r, uint32_t addr) {
    asm volatile("ldmatrix.sync.aligned.m8n8.x4.shared.b16 {%0,%1,%2,%3}, [%4];"
        : "=r"(r[0]), "=r"(r[1]), "=r"(r[2]), "=r"(r[3]) : "r"(addr));
}
__device__ __forceinline__ void mma_bf16(float* c, const uint32_t* a, const uint32_t* b) {
    asm volatile("mma.sync.aligned.m16n8k16.row.col.f32.bf16.bf16.f32 "
        "{%0,%1,%2,%3}, {%4,%5,%6,%7}, {%8,%9}, {%0,%1,%2,%3};"
        : "+f"(c[0]), "+f"(c[1]), "+f"(c[2]), "+f"(c[3])
        : "r"(a[0]), "r"(a[1]), "r"(a[2]), "r"(a[3]), "r"(b[0]), "r"(b[1]));
}

// ---------------------------------------------------------------------------
// Kernel 1 (convert + qh), 3 roles by blockIdx  (unchanged — passing)
// ---------------------------------------------------------------------------
__global__ __launch_bounds__(256) void convert_kernel(const int* __restrict__ Xq,
                                                      const float* __restrict__ qemb,
                                                      const float* __restrict__ kemb,
                                                      const float* __restrict__ W1) {
    __shared__ union {
        float tr[32][33];
        float qs[Dd][4];
    } sm;
    int t = threadIdx.x;
    int bid = blockIdx.x;

    if (bid < 256) {
#pragma unroll
        for (int j = 0; j < 8; ++j) {
            size_t i = (size_t)bid * 8192 + j * 1024 + t * 4;
            float4 v = *(const float4*)&kemb[i];
            unsigned short h0, l0, h1, l1, h2, l2, h3, l3;
            split_bf16(v.x, h0, l0); split_bf16(v.y, h1, l1);
            split_bf16(v.z, h2, l2); split_bf16(v.w, h3, l3);
            *(unsigned long long*)&g_Ah[i] =
                (unsigned long long)h0 | ((unsigned long long)h1 << 16) |
                ((unsigned long long)h2 << 32) | ((unsigned long long)h3 << 48);
            *(unsigned long long*)&g_Al[i] =
                (unsigned long long)l0 | ((unsigned long long)l1 << 16) |
                ((unsigned long long)l2 << 32) | ((unsigned long long)l3 << 48);
        }
    } else if (bid < 512) {
        const float* W1b = W1 + (size_t)Dd * Hh;
        int tt = bid - 256;
        int kb = (tt >> 4) * 32;
        int nb = (tt & 15) * 32;
        int r  = t >> 3;
        int c4 = (t & 7) * 4;
        float4 v = *(const float4*)&W1b[(size_t)(kb + r) * Hh + nb + c4];
        sm.tr[r][c4 + 0] = v.x; sm.tr[r][c4 + 1] = v.y;
        sm.tr[r][c4 + 2] = v.z; sm.tr[r][c4 + 3] = v.w;
        __syncthreads();
        unsigned long long hv = 0, lv = 0;
#pragma unroll
        for (int j = 0; j < 4; ++j) {
            unsigned short h, l;
            split_bf16(sm.tr[c4 + j][r], h, l);
            hv |= (unsigned long long)h << (16 * j);
            lv |= (unsigned long long)l << (16 * j);
        }
        size_t o = (size_t)(nb + r) * Dd + kb + c4;
        *(unsigned long long*)&g_Bth[o] = hv;
        *(unsigned long long*)&g_Btl[o] = lv;
    } else {
        int r  = bid - 512;
        int hc = r & 1;
        int bg = r >> 1;
        int h  = hc * 256 + t;
        int b0 = bg * 4;

        int bi   = t >> 6;
        int lane64 = t & 63;
        const float* qrow = qemb + (size_t)Xq[b0 + bi] * Dd;
#pragma unroll
        for (int j = 0; j < 8; ++j) {
            int d = lane64 + 64 * j;
            sm.qs[d][bi] = qrow[d];
        }
        __syncthreads();

        const float* w = W1 + h;
        unsigned long long acc01 = 0ULL, acc23 = 0ULL;
#pragma unroll 8
        for (int d = 0; d < Dd; ++d) {
            float wv = w[(size_t)d * Hh];
            float4 q4 = *(const float4*)&sm.qs[d][0];
            unsigned long long ws = pack2(wv, wv);
            fma2(acc01, pack2(q4.x, q4.y), ws);
            fma2(acc23, pack2(q4.z, q4.w), ws);
        }
        float2 p01 = unpack2(acc01);
        float2 p23 = unpack2(acc23);
        g_qh[(b0 + 0) * Hh + h] = p01.x;
        g_qh[(b0 + 1) * Hh + h] = p01.y;
        g_qh[(b0 + 2) * Hh + h] = p23.x;
        g_qh[(b0 + 3) * Hh + h] = p23.y;
    }
}

// ---------------------------------------------------------------------------
// Kernel 2: kh' = key @ W1b + b1 via bf16 mma.sync  (unchanged — passing)
// ---------------------------------------------------------------------------
#define APITCH 24
#define BUFE   (128 * APITCH)
#define BUFB   (BUFE * 2)

__global__ __launch_bounds__(256, 1) void kh_gemm(const float* __restrict__ b1) {
    __shared__ __nv_bfloat16 smbuf[4 * BUFE];

    int t    = threadIdx.x;
    int wid  = t >> 5;
    int lane = t & 31;
    int m0 = (blockIdx.x >> 2) * 128;
    int n0 = (blockIdx.x & 3) * 128;
    int wm0 = (wid & 1) * 64;
    int wn0 = (wid >> 1) * 32;

    uint32_t sbase = smem_u32(smbuf);
    uint32_t sA = sbase;
    uint32_t sB = sbase + 2 * BUFB;

    uint32_t aoff[4], boff[2];
#pragma unroll
    for (int mt = 0; mt < 4; ++mt)
        aoff[mt] = ((wm0 + mt * 16 + (lane & 15)) * APITCH + (lane >> 4) * 8) * 2;
    {
        int quad = lane >> 3, l8 = lane & 7;
#pragma unroll
        for (int p = 0; p < 2; ++p)
            boff[p] = ((wn0 + 16 * p + (quad >> 1) * 8 + l8) * APITCH + (quad & 1) * 8) * 2;
    }

    int srow = t >> 1;
    int shalf = (t & 1) * 8;
    __nv_bfloat16* stA = &smbuf[srow * APITCH + shalf];
    __nv_bfloat16* stB = &smbuf[2 * BUFE + srow * APITCH + shalf];

    float acc[4][4][4];
#pragma unroll
    for (int i = 0; i < 4; ++i)
#pragma unroll
        for (int j = 0; j < 4; ++j)
#pragma unroll
            for (int p = 0; p < 4; ++p) acc[i][j][p] = 0.f;

    const __nv_bfloat16* Aplane[3] = {g_Ah, g_Al, g_Ah};
    const __nv_bfloat16* Bplane[3] = {g_Bth, g_Bth, g_Btl};

    uint4 aR = *(const uint4*)&g_Ah[(size_t)(m0 + srow) * Dd + shalf];
    uint4 bR = *(const uint4*)&g_Bth[(size_t)(n0 + srow) * Dd + shalf];
    *(uint4*)stA = aR;
    *(uint4*)stB = bR;
    __syncthreads();

    const int NSTEP = 96;
    for (int s = 0; s < NSTEP; ++s) {
        int cur = s & 1;

        if (s + 1 < NSTEP) {
            int seg = (s + 1) >> 5;
            int kk  = ((s + 1) & 31) << 4;
            aR = *(const uint4*)&Aplane[seg][(size_t)(m0 + srow) * Dd + kk + shalf];
            bR = *(const uint4*)&Bplane[seg][(size_t)(n0 + srow) * Dd + kk + shalf];
        }

        uint32_t a[4][4], bfr[4][2];
        uint32_t cA = sA + cur * BUFB;
        uint32_t cB = sB + cur * BUFB;
#pragma unroll
        for (int mt = 0; mt < 4; ++mt) ldmx4(a[mt], cA + aoff[mt]);
#pragma unroll
        for (int p = 0; p < 2; ++p) {
            uint32_t r[4];
            ldmx4(r, cB + boff[p]);
            bfr[2 * p][0] = r[0]; bfr[2 * p][1] = r[1];
            bfr[2 * p + 1][0] = r[2]; bfr[2 * p + 1][1] = r[3];
        }
#pragma unroll
        for (int mt = 0; mt < 4; ++mt)
#pragma unroll
            for (int nt = 0; nt < 4; ++nt)
                mma_bf16(acc[mt][nt], a[mt], bfr[nt]);

        if (s + 1 < NSTEP) {
            int nxt = cur ^ 1;
            *(uint4*)(stA + nxt * BUFE) = aR;
            *(uint4*)(stB + nxt * BUFE) = bR;
        }
        __syncthreads();
    }

#pragma unroll
    for (int mt = 0; mt < 4; ++mt) {
        int rg = m0 + wm0 + mt * 16 + (lane >> 2);
#pragma unroll
        for (int nt = 0; nt < 4; ++nt) {
            int ng = n0 + wn0 + nt * 8 + (lane & 3) * 2;
            float2 bv = *(const float2*)&b1[ng];
            *(float2*)&g_kh[(size_t)rg * Hh + ng] =
                make_float2(acc[mt][nt][0] + bv.x, acc[mt][nt][1] + bv.y);
            *(float2*)&g_kh[(size_t)(rg + 8) * Hh + ng] =
                make_float2(acc[mt][nt][2] + bv.x, acc[mt][nt][3] + bv.y);
        }
    }
}

// ---------------------------------------------------------------------------
// Kernel 3 (v4): logits partials, broadcast-q register design.
// Grid 256 = 64 k-tiles x 4 h-quarters. Block 256 thr: tk=t&31 (2k each ->
// 64k), bg=t>>5 (warp-uniform b-group of 8 b; all 64 b covered).
// Per warp-h: 1 LDS.64 (kk, conflict-free) + 8 LDS.64 broadcasts (qq) +
// 24 fma-pipe packed ops -> ~0.5 B smem per contribution (was 4 B).
// Exact packed relu (s + |s| = 2*relu(s)) with w/2 pre-folded.
// ---------------------------------------------------------------------------
#define CH 32
#define LPITCH 66    // floats/ULLs per row: conflict-free LDS.64 reads
#define LP_KS_BUF  (CH * LPITCH)            // floats per ks buffer
#define LP_QS_BUF  (CH * LPITCH)            // ULLs per qsp buffer
#define LP_SMEM (2*LP_KS_BUF*4 + 2*LP_QS_BUF*8 + 128*8)   // 51712 bytes

__global__ __launch_bounds__(256) void logits_partial(const float* __restrict__ W2) {
    extern __shared__ char lsm[];
    float* ks = (float*)lsm;                                   // [2][CH][LPITCH]
    unsigned long long* qsp = (unsigned long long*)(lsm + 2 * LP_KS_BUF * 4);
    unsigned long long* w2p = (unsigned long long*)(lsm + 2 * LP_KS_BUF * 4 + 2 * LP_QS_BUF * 8);

    const unsigned long long ABSM = 0x7FFFFFFF7FFFFFFFULL;

    int t  = threadIdx.x;
    int tk = t & 31;                 // 2 k at k0 + 2*tk
    int bg = t >> 5;                 // warp-uniform b-group (8 b)
    int bx = blockIdx.x;
    int k0 = (bx & 63) * 64;
    int hq = bx >> 6;                // 0..3
    int hbase = hq * 128;

    // w2 packed once per block (w/2 folded)
    if (t < 128) {
        float wv = W2[hbase + t] * 0.5f;
        w2p[t] = pack2(wv, wv);
    }

    // stage chunk 0 into buffer 0
#pragma unroll
    for (int i = 0; i < 8; ++i) {
        int lin = t + i * 256;                       // 0..2047
        int k = lin >> 5, hh = lin & 31;
        ks[hh * LPITCH + k] = g_kh[(size_t)(k0 + k) * Hh + hbase + hh];
    }
#pragma unroll
    for (int i = 0; i < 8; ++i) {
        int lin = t + i * 256;                       // 0..2047 (64 b x 32 h)
        int b = lin >> 5, hh = lin & 31;
        float qv = g_qh[b * Hh + hbase + hh];
        qsp[hh * LPITCH + b] = pack2(qv, qv);
    }
    __syncthreads();

    unsigned long long acc[8] = {0ULL,0ULL,0ULL,0ULL,0ULL,0ULL,0ULL,0ULL};

    for (int cc = 0; cc < 4; ++cc) {
        int cur = cc & 1;
        int nxt = cur ^ 1;

        // prefetch chunk cc+1 into registers
        float pk[8], pq[8];
        if (cc < 3) {
            int h0n = hbase + (cc + 1) * CH;
#pragma unroll
            for (int i = 0; i < 8; ++i) {
                int lin = t + i * 256;
                int k = lin >> 5, hh = lin & 31;
                pk[i] = g_kh[(size_t)(k0 + k) * Hh + h0n + hh];
            }
#pragma unroll
            for (int i = 0; i < 8; ++i) {
                int lin = t + i * 256;
                int b = lin >> 5, hh = lin & 31;
                pq[i] = g_qh[b * Hh + h0n + hh];
            }
        }

        // compute chunk cc from buffer cur
        const float* ksc = ks + cur * LP_KS_BUF;
        const unsigned long long* qsc = qsp + cur * LP_QS_BUF;
#pragma unroll 4
        for (int hh = 0; hh < CH; ++hh) {
            unsigned long long kk = *(const unsigned long long*)&ksc[hh * LPITCH + 2 * tk];
            unsigned long long w2 = w2p[cc * CH + hh];
            const unsigned long long* qrow = &qsc[hh * LPITCH + bg * 8];
#pragma unroll
            for (int bi = 0; bi < 8; ++bi) {
                unsigned long long s = add2(qrow[bi], kk);
                s = add2(s, s & ABSM);               // = 2*relu, exact
                fma2(acc[bi], s, w2);
            }
        }

        // commit prefetched chunk into the other buffer
        if (cc < 3) {
#pragma unroll
            for (int i = 0; i < 8; ++i) {
                int lin = t + i * 256;
                int k = lin >> 5, hh = lin & 31;
                ks[nxt * LP_KS_BUF + hh * LPITCH + k] = pk[i];
            }
#pragma unroll
            for (int i = 0; i < 8; ++i) {
                int lin = t + i * 256;
                int b = lin >> 5, hh = lin & 31;
                qsp[nxt * LP_QS_BUF + hh * LPITCH + b] = pack2(pq[i], pq[i]);
            }
        }
        __syncthreads();
    }

    // write partials: 8 b x 2 k per thread, coalesced float2
    float* base = &g_part[(size_t)hq * Bq * Kk];
#pragma unroll
    for (int bi = 0; bi < 8; ++bi) {
        int b = bg * 8 + bi;
        float2 r = unpack2(acc[bi]);
        *(float2*)&base[(size_t)b * Kk + k0 + 2 * tk] = r;
    }
}

// ---------------------------------------------------------------------------
// Kernel 4 (v3): out = sum of 4 partials + b2.  float4 grain.
// ---------------------------------------------------------------------------
__global__ __launch_bounds__(256) void logits_reduce(const float* __restrict__ b2,
                                                     float* __restrict__ out) {
    int i = blockIdx.x * 256 + threadIdx.x;          // 65536 float4 slots
    const float4* p0 = (const float4*)&g_part[0 * Bq * Kk];
    const float4* p1 = (const float4*)&g_part[1 * Bq * Kk];
    const float4* p2 = (const float4*)&g_part[2 * Bq * Kk];
    const float4* p3 = (const float4*)&g_part[3 * Bq * Kk];
    float bias = b2[0];
    float4 a = p0[i], b = p1[i], c = p2[i], d = p3[i];
    ((float4*)out)[i] = make_float4(a.x + b.x + c.x + d.x + bias,
                                    a.y + b.y + c.y + d.y + bias,
                                    a.z + b.z + c.z + d.z + bias,
                                    a.w + b.w + c.w + d.w + bias);
}

// ---------------------------------------------------------------------------
// Inputs (metadata order): X_query(int32, 64), query_embed(f32, 8192x512),
// key_embed(f32, 4096x512), W1(f32, 1024x512), b1(f32, 512),
// W2(f32, 512x1), b2(f32, 1). Output: f32, 64x4096.
// ---------------------------------------------------------------------------
extern "C" void kernel_launch(void* const* d_in, const int* in_sizes, int n_in,
                              void* d_out, int out_size) {
    const int*   Xq   = (const int*)d_in[0];
    const float* qemb = (const float*)d_in[1];
    const float* kemb = (const float*)d_in[2];
    const float* W1   = (const float*)d_in[3];
    const float* b1   = (const float*)d_in[4];
    const float* W2   = (const float*)d_in[5];
    const float* b2   = (const float*)d_in[6];
    float* out = (float*)d_out;

    cudaFuncSetAttribute(logits_partial, cudaFuncAttributeMaxDynamicSharedMemorySize, LP_SMEM);

    convert_kernel<<<544, 256>>>(Xq, qemb, kemb, W1);   // split A/B + qh
    kh_gemm<<<128, 256>>>(b1);                          // tensor-core kh
    logits_partial<<<256, 256, LP_SMEM>>>(W2);          // broadcast-q relu-reduce
    logits_reduce<<<256, 256>>>(b2, out);               // combine + b2
}

// round 11
// speedup vs baseline: 1.3926x; 1.3384x over previous
#include <cuda_runtime.h>
#include <cuda_bf16.h>
#include <cstdint>

// Problem constants
#define Bq   64
#define Kk   4096
#define Dd   512
#define Hh   512

// Scratch (no cudaMalloc allowed)
__device__ float g_qh[Bq * Hh];
__device__ float g_kh[Kk * Hh];
__device__ float g_part[4 * Bq * Kk];    // 4 h-quarter partials

// ---------------------------------------------------------------------------
// f32x2 packed helpers
// ---------------------------------------------------------------------------
__device__ __forceinline__ unsigned long long pack2(float x, float y) {
    unsigned long long r;
    asm("mov.b64 %0, {%1, %2};" : "=l"(r) : "r"(__float_as_uint(x)), "r"(__float_as_uint(y)));
    return r;
}
__device__ __forceinline__ void fma2(unsigned long long& d,
                                     unsigned long long a, unsigned long long b) {
    asm("fma.rn.f32x2 %0, %1, %2, %0;" : "+l"(d) : "l"(a), "l"(b));
}
__device__ __forceinline__ unsigned long long add2(unsigned long long a,
                                                   unsigned long long b) {
    unsigned long long r;
    asm("add.rn.f32x2 %0, %1, %2;" : "=l"(r) : "l"(a), "l"(b));
    return r;
}
__device__ __forceinline__ float2 unpack2(unsigned long long v) {
    unsigned int lo, hi;
    asm("mov.b64 {%0, %1}, %2;" : "=r"(lo), "=r"(hi) : "l"(v));
    return make_float2(__uint_as_float(lo), __uint_as_float(hi));
}

// fp32 -> (hi, lo) bf16 split
__device__ __forceinline__ void split_bf16(float x, unsigned short& hi, unsigned short& lo) {
    __nv_bfloat16 h = __float2bfloat16_rn(x);
    float r = x - __bfloat162float(h);
    __nv_bfloat16 l = __float2bfloat16_rn(r);
    hi = __bfloat16_as_ushort(h);
    lo = __bfloat16_as_ushort(l);
}
// split 8 fp32 -> two uint4 (hi plane, lo plane)
__device__ __forceinline__ void split8(const float* v, uint4& hv, uint4& lv) {
    unsigned short h[8], l[8];
#pragma unroll
    for (int i = 0; i < 8; ++i) split_bf16(v[i], h[i], l[i]);
    hv.x = (uint32_t)h[0] | ((uint32_t)h[1] << 16);
    hv.y = (uint32_t)h[2] | ((uint32_t)h[3] << 16);
    hv.z = (uint32_t)h[4] | ((uint32_t)h[5] << 16);
    hv.w = (uint32_t)h[6] | ((uint32_t)h[7] << 16);
    lv.x = (uint32_t)l[0] | ((uint32_t)l[1] << 16);
    lv.y = (uint32_t)l[2] | ((uint32_t)l[3] << 16);
    lv.z = (uint32_t)l[4] | ((uint32_t)l[5] << 16);
    lv.w = (uint32_t)l[6] | ((uint32_t)l[7] << 16);
}

__device__ __forceinline__ uint32_t smem_u32(const void* p) {
    uint32_t a;
    asm("{ .reg .u64 t; cvta.to.shared.u64 t, %1; cvt.u32.u64 %0, t; }" : "=r"(a) : "l"(p));
    return a;
}

// ---------------------------------------------------------------------------
// mma.sync helpers (sm_80 PTX — safe on the sm_100 ptxas target)
// ---------------------------------------------------------------------------
__device__ __forceinline__ void ldmx4(uint32_t* r, uint32_t addr) {
    asm volatile("ldmatrix.sync.aligned.m8n8.x4.shared.b16 {%0,%1,%2,%3}, [%4];"
        : "=r"(r[0]), "=r"(r[1]), "=r"(r[2]), "=r"(r[3]) : "r"(addr));
}
__device__ __forceinline__ void mma_bf16(float* c, const uint32_t* a, const uint32_t* b) {
    asm volatile("mma.sync.aligned.m16n8k16.row.col.f32.bf16.bf16.f32 "
        "{%0,%1,%2,%3}, {%4,%5,%6,%7}, {%8,%9}, {%0,%1,%2,%3};"
        : "+f"(c[0]), "+f"(c[1]), "+f"(c[2]), "+f"(c[3])
        : "r"(a[0]), "r"(a[1]), "r"(a[2]), "r"(a[3]), "r"(b[0]), "r"(b[1]));
}

// ---------------------------------------------------------------------------
// Fused kernel: blocks [0,128) = kh' = key @ W1b + b1 (bf16 mma, in-kernel
// 3-term split: Ah*Bh + Al*Bh + Ah*Bl, residual Al*Bl ~ 2^-18);
// blocks [128,160) = qh = gather(query_embed) @ W1[:D]  (SIMT f32x2).
//
// Per 16-k chunk: load fp32 A(128x16)+B(16x128) ONCE, split to 4 bf16 smem
// tiles, run all 3 MMA segments (Ah/Bh fragments reused in registers).
// Double-buffered; 32 steps, 32 barriers (was 96).
// ---------------------------------------------------------------------------
#define TPITCH 24                      // bf16 pitch per tile row (48 B)
#define TILE_E (128 * TPITCH)          // 3072 elems = 6144 B per tile
#define BUF_E  (4 * TILE_E)            // Ah Al Bh Bl = 12288 elems = 24576 B
#define KH_SMEM (2 * BUF_E * 2)        // 49152 bytes

__global__ __launch_bounds__(256) void fused_kh(const int* __restrict__ Xq,
                                                const float* __restrict__ qemb,
                                                const float* __restrict__ kemb,
                                                const float* __restrict__ W1,
                                                const float* __restrict__ b1) {
    extern __shared__ char lsm[];
    int t    = threadIdx.x;
    int wid  = t >> 5;
    int lane = t & 31;

    if (blockIdx.x < 128) {
        // =================== kh role ===================
        __nv_bfloat16* smb = (__nv_bfloat16*)lsm;
        const float* W1b = W1 + (size_t)Dd * Hh;
        int m0 = (blockIdx.x >> 2) * 128;
        int n0 = (blockIdx.x & 3) * 128;
        int wm0 = (wid & 1) * 64;
        int wn0 = (wid >> 1) * 32;

        uint32_t sbase = smem_u32(smb);

        // ldmatrix per-lane byte offsets within one tile
        uint32_t aoff[4], boff[2];
#pragma unroll
        for (int mt = 0; mt < 4; ++mt)
            aoff[mt] = ((wm0 + mt * 16 + (lane & 15)) * TPITCH + (lane >> 4) * 8) * 2;
        {
            int quad = lane >> 3, l8 = lane & 7;
#pragma unroll
            for (int p = 0; p < 2; ++p)
                boff[p] = ((wn0 + 16 * p + (quad >> 1) * 8 + l8) * TPITCH + (quad & 1) * 8) * 2;
        }

        // staging mapping
        int arow = t >> 1, acol8 = (t & 1) * 8;   // A: row m, 8 consecutive k
        int bn   = t >> 1, bkh   = (t & 1) * 8;   // B: col n, 8 consecutive k (strided fp32 loads)

        float acc[4][4][4];
#pragma unroll
        for (int i = 0; i < 4; ++i)
#pragma unroll
            for (int j = 0; j < 4; ++j)
#pragma unroll
                for (int p = 0; p < 4; ++p) acc[i][j][p] = 0.f;

        // ---- load + convert + store step 0 into buffer 0 ----
        {
            float av[8];
            *(float4*)&av[0] = *(const float4*)&kemb[(size_t)(m0 + arow) * Dd + acol8];
            *(float4*)&av[4] = *(const float4*)&kemb[(size_t)(m0 + arow) * Dd + acol8 + 4];
            uint4 ah, al; split8(av, ah, al);
            float bv[8];
#pragma unroll
            for (int j = 0; j < 8; ++j)
                bv[j] = W1b[(size_t)(bkh + j) * Hh + n0 + bn];
            uint4 bh, bl; split8(bv, bh, bl);
            *(uint4*)&smb[arow * TPITCH + acol8]              = ah;
            *(uint4*)&smb[TILE_E + arow * TPITCH + acol8]     = al;
            *(uint4*)&smb[2 * TILE_E + bn * TPITCH + bkh]     = bh;
            *(uint4*)&smb[3 * TILE_E + bn * TPITCH + bkh]     = bl;
        }
        __syncthreads();

        for (int s = 0; s < 32; ++s) {
            int cur = s & 1;
            uint32_t bufb = sbase + cur * (BUF_E * 2);

            // prefetch + convert next chunk
            uint4 ahn, aln, bhn, bln;
            if (s + 1 < 32) {
                int kk = (s + 1) * 16;
                float av[8];
                *(float4*)&av[0] = *(const float4*)&kemb[(size_t)(m0 + arow) * Dd + kk + acol8];
                *(float4*)&av[4] = *(const float4*)&kemb[(size_t)(m0 + arow) * Dd + kk + acol8 + 4];
                split8(av, ahn, aln);
                float bv[8];
#pragma unroll
                for (int j = 0; j < 8; ++j)
                    bv[j] = W1b[(size_t)(kk + bkh + j) * Hh + n0 + bn];
                split8(bv, bhn, bln);
            }

            // ---- compute: 3 segments from buffer cur ----
            uint32_t ah[4][4], al[4][4], bhf[4][2], blf[4][2];
#pragma unroll
            for (int mt = 0; mt < 4; ++mt) ldmx4(ah[mt], bufb + aoff[mt]);
#pragma unroll
            for (int p = 0; p < 2; ++p) {
                uint32_t r[4];
                ldmx4(r, bufb + 2 * TILE_E * 2 + boff[p]);
                bhf[2 * p][0] = r[0]; bhf[2 * p][1] = r[1];
                bhf[2 * p + 1][0] = r[2]; bhf[2 * p + 1][1] = r[3];
            }
            // seg0: Ah * Bh
#pragma unroll
            for (int mt = 0; mt < 4; ++mt)
#pragma unroll
                for (int nt = 0; nt < 4; ++nt)
                    mma_bf16(acc[mt][nt], ah[mt], bhf[nt]);
            // seg2: Ah * Bl (Ah still in registers)
#pragma unroll
            for (int p = 0; p < 2; ++p) {
                uint32_t r[4];
                ldmx4(r, bufb + 3 * TILE_E * 2 + boff[p]);
                blf[2 * p][0] = r[0]; blf[2 * p][1] = r[1];
                blf[2 * p + 1][0] = r[2]; blf[2 * p + 1][1] = r[3];
            }
#pragma unroll
            for (int mt = 0; mt < 4; ++mt)
#pragma unroll
                for (int nt = 0; nt < 4; ++nt)
                    mma_bf16(acc[mt][nt], ah[mt], blf[nt]);
            // seg1: Al * Bh (Bh still in registers)
#pragma unroll
            for (int mt = 0; mt < 4; ++mt) ldmx4(al[mt], bufb + TILE_E * 2 + aoff[mt]);
#pragma unroll
            for (int mt = 0; mt < 4; ++mt)
#pragma unroll
                for (int nt = 0; nt < 4; ++nt)
                    mma_bf16(acc[mt][nt], al[mt], bhf[nt]);

            // ---- commit prefetched chunk into other buffer ----
            if (s + 1 < 32) {
                int nxt = cur ^ 1;
                __nv_bfloat16* bb = smb + nxt * BUF_E;
                *(uint4*)&bb[arow * TPITCH + acol8]          = ahn;
                *(uint4*)&bb[TILE_E + arow * TPITCH + acol8] = aln;
                *(uint4*)&bb[2 * TILE_E + bn * TPITCH + bkh] = bhn;
                *(uint4*)&bb[3 * TILE_E + bn * TPITCH + bkh] = bln;
            }
            __syncthreads();
        }

        // epilogue: + b1 -> g_kh
#pragma unroll
        for (int mt = 0; mt < 4; ++mt) {
            int rg = m0 + wm0 + mt * 16 + (lane >> 2);
#pragma unroll
            for (int nt = 0; nt < 4; ++nt) {
                int ng = n0 + wn0 + nt * 8 + (lane & 3) * 2;
                float2 bv = *(const float2*)&b1[ng];
                *(float2*)&g_kh[(size_t)rg * Hh + ng] =
                    make_float2(acc[mt][nt][0] + bv.x, acc[mt][nt][1] + bv.y);
                *(float2*)&g_kh[(size_t)(rg + 8) * Hh + ng] =
                    make_float2(acc[mt][nt][2] + bv.x, acc[mt][nt][3] + bv.y);
            }
        }
    } else {
        // =================== qh role: 4 b x 256 h (SIMT, exact fp32) ========
        float (*qs)[4] = (float(*)[4])lsm;       // [512][4] = 8 KB
        int r  = blockIdx.x - 128;
        int hc = r & 1;
        int bg = r >> 1;
        int h  = hc * 256 + t;
        int b0 = bg * 4;

        int bi   = t >> 6;
        int lane64 = t & 63;
        const float* qrow = qemb + (size_t)Xq[b0 + bi] * Dd;
#pragma unroll
        for (int j = 0; j < 8; ++j) {
            int d = lane64 + 64 * j;
            qs[d][bi] = qrow[d];
        }
        __syncthreads();

        const float* w = W1 + h;
        unsigned long long acc01 = 0ULL, acc23 = 0ULL;
#pragma unroll 8
        for (int d = 0; d < Dd; ++d) {
            float wv = w[(size_t)d * Hh];
            float4 q4 = *(const float4*)&qs[d][0];
            unsigned long long ws = pack2(wv, wv);
            fma2(acc01, pack2(q4.x, q4.y), ws);
            fma2(acc23, pack2(q4.z, q4.w), ws);
        }
        float2 p01 = unpack2(acc01);
        float2 p23 = unpack2(acc23);
        g_qh[(b0 + 0) * Hh + h] = p01.x;
        g_qh[(b0 + 1) * Hh + h] = p01.y;
        g_qh[(b0 + 2) * Hh + h] = p23.x;
        g_qh[(b0 + 3) * Hh + h] = p23.y;
    }
}

// ---------------------------------------------------------------------------
// logits_partial v4 (unchanged): broadcast-q register design.
// Grid 256 = 64 k-tiles x 4 h-quarters; thread = 2k x 8b (warp-uniform b).
// Exact packed relu (s + |s| = 2*relu(s)) with w/2 pre-folded.
// ---------------------------------------------------------------------------
#define CH 32
#define LPITCH 66
#define LP_KS_BUF  (CH * LPITCH)
#define LP_QS_BUF  (CH * LPITCH)
#define LP_SMEM (2*LP_KS_BUF*4 + 2*LP_QS_BUF*8 + 128*8)

__global__ __launch_bounds__(256) void logits_partial(const float* __restrict__ W2) {
    extern __shared__ char lsm[];
    float* ks = (float*)lsm;
    unsigned long long* qsp = (unsigned long long*)(lsm + 2 * LP_KS_BUF * 4);
    unsigned long long* w2p = (unsigned long long*)(lsm + 2 * LP_KS_BUF * 4 + 2 * LP_QS_BUF * 8);

    const unsigned long long ABSM = 0x7FFFFFFF7FFFFFFFULL;

    int t  = threadIdx.x;
    int tk = t & 31;
    int bg = t >> 5;
    int bx = blockIdx.x;
    int k0 = (bx & 63) * 64;
    int hq = bx >> 6;
    int hbase = hq * 128;

    if (t < 128) {
        float wv = W2[hbase + t] * 0.5f;
        w2p[t] = pack2(wv, wv);
    }

#pragma unroll
    for (int i = 0; i < 8; ++i) {
        int lin = t + i * 256;
        int k = lin >> 5, hh = lin & 31;
        ks[hh * LPITCH + k] = g_kh[(size_t)(k0 + k) * Hh + hbase + hh];
    }
#pragma unroll
    for (int i = 0; i < 8; ++i) {
        int lin = t + i * 256;
        int b = lin >> 5, hh = lin & 31;
        float qv = g_qh[b * Hh + hbase + hh];
        qsp[hh * LPITCH + b] = pack2(qv, qv);
    }
    __syncthreads();

    unsigned long long acc[8] = {0ULL,0ULL,0ULL,0ULL,0ULL,0ULL,0ULL,0ULL};

    for (int cc = 0; cc < 4; ++cc) {
        int cur = cc & 1;
        int nxt = cur ^ 1;

        float pk[8], pq[8];
        if (cc < 3) {
            int h0n = hbase + (cc + 1) * CH;
#pragma unroll
            for (int i = 0; i < 8; ++i) {
                int lin = t + i * 256;
                int k = lin >> 5, hh = lin & 31;
                pk[i] = g_kh[(size_t)(k0 + k) * Hh + h0n + hh];
            }
#pragma unroll
            for (int i = 0; i < 8; ++i) {
                int lin = t + i * 256;
                int b = lin >> 5, hh = lin & 31;
                pq[i] = g_qh[b * Hh + h0n + hh];
            }
        }

        const float* ksc = ks + cur * LP_KS_BUF;
        const unsigned long long* qsc = qsp + cur * LP_QS_BUF;
#pragma unroll 4
        for (int hh = 0; hh < CH; ++hh) {
            unsigned long long kk = *(const unsigned long long*)&ksc[hh * LPITCH + 2 * tk];
            unsigned long long w2 = w2p[cc * CH + hh];
            const unsigned long long* qrow = &qsc[hh * LPITCH + bg * 8];
#pragma unroll
            for (int bi = 0; bi < 8; ++bi) {
                unsigned long long s = add2(qrow[bi], kk);
                s = add2(s, s & ABSM);
                fma2(acc[bi], s, w2);
            }
        }

        if (cc < 3) {
#pragma unroll
            for (int i = 0; i < 8; ++i) {
                int lin = t + i * 256;
                int k = lin >> 5, hh = lin & 31;
                ks[nxt * LP_KS_BUF + hh * LPITCH + k] = pk[i];
            }
#pragma unroll
            for (int i = 0; i < 8; ++i) {
                int lin = t + i * 256;
                int b = lin >> 5, hh = lin & 31;
                qsp[nxt * LP_QS_BUF + hh * LPITCH + b] = pack2(pq[i], pq[i]);
            }
        }
        __syncthreads();
    }

    float* base = &g_part[(size_t)hq * Bq * Kk];
#pragma unroll
    for (int bi = 0; bi < 8; ++bi) {
        int b = bg * 8 + bi;
        float2 r = unpack2(acc[bi]);
        *(float2*)&base[(size_t)b * Kk + k0 + 2 * tk] = r;
    }
}

// ---------------------------------------------------------------------------
// logits_reduce: out = sum of 4 partials + b2.  float4 grain.
// ---------------------------------------------------------------------------
__global__ __launch_bounds__(256) void logits_reduce(const float* __restrict__ b2,
                                                     float* __restrict__ out) {
    int i = blockIdx.x * 256 + threadIdx.x;
    const float4* p0 = (const float4*)&g_part[0 * Bq * Kk];
    const float4* p1 = (const float4*)&g_part[1 * Bq * Kk];
    const float4* p2 = (const float4*)&g_part[2 * Bq * Kk];
    const float4* p3 = (const float4*)&g_part[3 * Bq * Kk];
    float bias = b2[0];
    float4 a = p0[i], b = p1[i], c = p2[i], d = p3[i];
    ((float4*)out)[i] = make_float4(a.x + b.x + c.x + d.x + bias,
                                    a.y + b.y + c.y + d.y + bias,
                                    a.z + b.z + c.z + d.z + bias,
                                    a.w + b.w + c.w + d.w + bias);
}

// ---------------------------------------------------------------------------
// Inputs (metadata order): X_query(int32, 64), query_embed(f32, 8192x512),
// key_embed(f32, 4096x512), W1(f32, 1024x512), b1(f32, 512),
// W2(f32, 512x1), b2(f32, 1). Output: f32, 64x4096.
// ---------------------------------------------------------------------------
extern "C" void kernel_launch(void* const* d_in, const int* in_sizes, int n_in,
                              void* d_out, int out_size) {
    const int*   Xq   = (const int*)d_in[0];
    const float* qemb = (const float*)d_in[1];
    const float* kemb = (const float*)d_in[2];
    const float* W1   = (const float*)d_in[3];
    const float* b1   = (const float*)d_in[4];
    const float* W2   = (const float*)d_in[5];
    const float* b2   = (const float*)d_in[6];
    float* out = (float*)d_out;

    cudaFuncSetAttribute(fused_kh, cudaFuncAttributeMaxDynamicSharedMemorySize, KH_SMEM);
    cudaFuncSetAttribute(logits_partial, cudaFuncAttributeMaxDynamicSharedMemorySize, LP_SMEM);

    fused_kh<<<160, 256, KH_SMEM>>>(Xq, qemb, kemb, W1, b1);  // split-in-kernel GEMM + qh
    logits_partial<<<256, 256, LP_SMEM>>>(W2);                // broadcast-q relu-reduce
    logits_reduce<<<256, 256>>>(b2, out);                     // combine + b2
}